// round 9
// baseline (speedup 1.0000x reference)
#include <cuda_runtime.h>
#include <cuda_bf16.h>
#include <cstdint>

// Problem constants
#define H   1024
#define B   64
#define S   512
#define W3H 3072            // W row stride (3*H)
#define BLKS_PER_B 16       // fused kernel: 16 blocks per batch entry
#define ROWS_PER_BLK 32
#define CHUNK_ROWS 2        // rows per TMA chunk (8 KB)
#define NCHUNK (ROWS_PER_BLK / CHUNK_ROWS)       // 16
#define CHUNK_BYTES (CHUNK_ROWS * H * 4)         // 8192
#define RING 3

// Scratch (zero-initialized at module load; every launch self-cleans, so each
// graph replay is deterministic).
__device__ float g_u2[H];
__device__ float g_scores[B * S];
__device__ int   g_cnt[B];
__device__ int   g_gcnt;

// ---------------------------------------------------------------------------
// mbarrier / bulk-copy PTX helpers
// ---------------------------------------------------------------------------
__device__ __forceinline__ uint32_t smem_u32(const void* p) {
    return (uint32_t)__cvta_generic_to_shared(p);
}
__device__ __forceinline__ void mbar_init(uint32_t a, uint32_t cnt) {
    asm volatile("mbarrier.init.shared.b64 [%0], %1;" :: "r"(a), "r"(cnt) : "memory");
}
__device__ __forceinline__ void mbar_expect(uint32_t a, uint32_t bytes) {
    asm volatile("mbarrier.arrive.expect_tx.shared.b64 _, [%0], %1;"
                 :: "r"(a), "r"(bytes) : "memory");
}
__device__ __forceinline__ void bulk_g2s(uint32_t dst, const void* src,
                                         uint32_t bytes, uint32_t mbar) {
    asm volatile("cp.async.bulk.shared::cta.global.mbarrier::complete_tx::bytes "
                 "[%0], [%1], %2, [%3];"
                 :: "r"(dst), "l"(src), "r"(bytes), "r"(mbar) : "memory");
}
__device__ __forceinline__ void mbar_wait(uint32_t a, uint32_t parity) {
    uint32_t done;
    do {
        asm volatile("{\n\t.reg .pred p;\n\t"
                     "mbarrier.try_wait.parity.shared.b64 p, [%1], %2, 0x989680;\n\t"
                     "selp.b32 %0, 1, 0, p;\n\t}"
                     : "=r"(done) : "r"(a), "r"(parity) : "memory");
    } while (!done);
}
__device__ __forceinline__ void fence_async_smem() {
    asm volatile("fence.proxy.async.shared::cta;" ::: "memory");
}

// ---------------------------------------------------------------------------
// Kernel 1: u2[k] += sum_h v[h] * W[h, 2H + k]       (g_u2 pre-zeroed)
// grid = (4, 64): 256 blocks, 16 h-rows per block -> fills the chip.
// ---------------------------------------------------------------------------
__global__ void k_u2(const float* __restrict__ W, const float* __restrict__ v) {
    const int tx = threadIdx.x & 63;
    const int ty = threadIdx.x >> 6;          // 0..3
    const int k4 = blockIdx.x * 64 + tx;
    const int h0 = blockIdx.y * 16 + ty;

    float4 acc = make_float4(0.f, 0.f, 0.f, 0.f);
#pragma unroll
    for (int j = 0; j < 4; j++) {
        const int h = h0 + j * 4;
        const float vh = __ldg(&v[h]);
        const float4 w = __ldg((const float4*)(W + (size_t)h * W3H + 2 * H) + k4);
        acc.x += vh * w.x; acc.y += vh * w.y; acc.z += vh * w.z; acc.w += vh * w.w;
    }

    __shared__ float4 sm[4][64];
    sm[ty][tx] = acc;
    __syncthreads();
    if (ty == 0) {
        float4 s = sm[0][tx];
#pragma unroll
        for (int j = 1; j < 4; j++) {
            const float4 p = sm[j][tx];
            s.x += p.x; s.y += p.y; s.z += p.z; s.w += p.w;
        }
        float* dst = g_u2 + k4 * 4;
        atomicAdd(dst + 0, s.x);
        atomicAdd(dst + 1, s.y);
        atomicAdd(dst + 2, s.z);
        atomicAdd(dst + 3, s.w);
    }
}

// ---------------------------------------------------------------------------
// Kernel 2: TMA-streamed scores + per-b softmax + self-clean.
// 1024 blocks x 128 threads, 32 rows/block, 16 chunks of 2 rows (8 KB),
// 3-stage cp.async.bulk ring, u2 held in registers (no per-chunk smem reread).
// 1024 blocks @ 8/SM-capable -> single wave, max/avg imbalance 1.4%.
// ---------------------------------------------------------------------------
__global__ void __launch_bounds__(128, 8)
k_fused(const float* __restrict__ enc, float* __restrict__ out) {
    __shared__ alignas(128) float s_buf[RING][CHUNK_ROWS][H];   // 24 KB
    __shared__ float s_part[CHUNK_ROWS][2];
    __shared__ alignas(8) unsigned long long s_mbar[RING];
    __shared__ int s_ticket;
    __shared__ float s_sm[128];

    const int tid  = threadIdx.x;
    const int warp = tid >> 5;        // 0..3
    const int lane = tid & 31;
    const int b    = blockIdx.x >> 4;
    const int row0 = blockIdx.x * ROWS_PER_BLK;

    const int r    = warp >> 1;       // row within chunk (0..1)
    const int half = warp & 1;        // which half of the row
    const int base = half * 512 + lane * 4;   // float index into row

    // u2 slice for this thread's fixed indices -> registers (16 floats)
    float4 u[4];
#pragma unroll
    for (int k = 0; k < 4; k++)
        u[k] = __ldcg(((const float4*)g_u2) + (base >> 2) + k * 32);

    uint32_t mb[RING], sb[RING];
#pragma unroll
    for (int i = 0; i < RING; i++) {
        mb[i] = smem_u32(&s_mbar[i]);
        sb[i] = smem_u32(&s_buf[i][0][0]);
    }

    if (tid == 0) {
#pragma unroll
        for (int i = 0; i < RING; i++) mbar_init(mb[i], 1);
        fence_async_smem();
#pragma unroll
        for (int i = 0; i < RING; i++) {
            mbar_expect(mb[i], CHUNK_BYTES);
            bulk_g2s(sb[i], enc + (size_t)(row0 + i * CHUNK_ROWS) * H,
                     CHUNK_BYTES, mb[i]);
        }
    }
    __syncthreads();

    for (int c = 0; c < NCHUNK; c++) {
        const int slot = c - (c / RING) * RING;
        mbar_wait(mb[slot], (c / RING) & 1);

        const float* rowp = &s_buf[slot][r][0];
        float acc = 0.f;
#pragma unroll
        for (int k = 0; k < 4; k++) {
            const float4 e = *(const float4*)(rowp + base + k * 128);
            acc += e.x * u[k].x + e.y * u[k].y + e.z * u[k].z + e.w * u[k].w;
        }
#pragma unroll
        for (int off = 16; off > 0; off >>= 1)
            acc += __shfl_xor_sync(0xffffffffu, acc, off);
        if (lane == 0) s_part[r][half] = acc;
        __syncthreads();                 // all reads of this slot done

        if (tid < CHUNK_ROWS)
            g_scores[row0 + c * CHUNK_ROWS + tid] = s_part[tid][0] + s_part[tid][1];

        if (tid == 0 && c + RING < NCHUNK) {
            fence_async_smem();
            mbar_expect(mb[slot], CHUNK_BYTES);
            bulk_g2s(sb[slot], enc + (size_t)(row0 + (c + RING) * CHUNK_ROWS) * H,
                     CHUNK_BYTES, mb[slot]);
        }
    }

    // --- single-thread release + ticket ---
    __syncthreads();
    if (tid == 0) {
        __threadfence();
        s_ticket = atomicAdd(&g_cnt[b], 1);
        if (s_ticket == BLKS_PER_B - 1)
            __threadfence();             // acquire for re-reads
    }
    __syncthreads();

    if (s_ticket == BLKS_PER_B - 1) {
        const float* sc = g_scores + b * S;
        float vv[4];
#pragma unroll
        for (int q = 0; q < 4; q++) vv[q] = __ldcg(&sc[tid + q * 128]);

        float m = fmaxf(fmaxf(vv[0], vv[1]), fmaxf(vv[2], vv[3]));
        s_sm[tid] = m;
        __syncthreads();
#pragma unroll
        for (int st = 64; st > 0; st >>= 1) {
            if (tid < st) s_sm[tid] = fmaxf(s_sm[tid], s_sm[tid + st]);
            __syncthreads();
        }
        const float mx = s_sm[0];
        __syncthreads();

        float e[4], esum = 0.f;
#pragma unroll
        for (int q = 0; q < 4; q++) { e[q] = __expf(vv[q] - mx); esum += e[q]; }
        s_sm[tid] = esum;
        __syncthreads();
#pragma unroll
        for (int st = 64; st > 0; st >>= 1) {
            if (tid < st) s_sm[tid] += s_sm[tid + st];
            __syncthreads();
        }
        const float inv = 1.f / s_sm[0];

#pragma unroll
        for (int q = 0; q < 4; q++)
            out[b * S + tid + q * 128] = e[q] * inv;

        // --- self-clean for the next launch ---
        if (tid == 0) {
            g_cnt[b] = 0;
            __threadfence();
            const int g = atomicAdd(&g_gcnt, 1);
            s_ticket = (g == B - 1) ? 1 : 0;
        }
        __syncthreads();
        if (s_ticket == 1) {
            ((float4*)g_u2)[tid]       = make_float4(0.f, 0.f, 0.f, 0.f);
            ((float4*)g_u2)[tid + 128] = make_float4(0.f, 0.f, 0.f, 0.f);
            if (tid == 0) g_gcnt = 0;
        }
    }
}

// ---------------------------------------------------------------------------
// Inputs (metadata order): hidden[2,B,H], encoder_outputs[B,S,H],
//                          W[H,3H], b[H], v[H]
// hidden and b are mathematically irrelevant post-softmax (per-row constants).
// ---------------------------------------------------------------------------
extern "C" void kernel_launch(void* const* d_in, const int* in_sizes, int n_in,
                              void* d_out, int out_size) {
    const float* enc = (const float*)d_in[1];
    const float* W   = (const float*)d_in[2];
    const float* v   = (const float*)d_in[4];
    float* out = (float*)d_out;

    {
        dim3 grid(4, 64);
        k_u2<<<grid, 256>>>(W, v);
    }
    k_fused<<<B * BLKS_PER_B, 128>>>(enc, out);
}